// round 11
// baseline (speedup 1.0000x reference)
#include <cuda_runtime.h>
#include <math.h>
#include <stdint.h>

#define BQ 64
#define NQ 2048
#define DQ 256
#define HQ 8
#define KDQ 32
#define VDQ 32
#define OQ 256
#define HV 256

// ---------------- scratch (static device arrays: no allocation) ----------------
__device__ float g_q[BQ * HQ * KDQ];
__device__ float g_v[(size_t)BQ * NQ * VDQ];
__device__ float g_logits[(size_t)BQ * HQ * NQ];
__device__ float g_wavg[BQ * HV];
// g_gated: per (tile, kc) fragment-image: [1024][8][128 rows][32 words]
__device__ float g_gated[(size_t)1024 * 8 * 4096];   // 128 MB
// packed B weight images: [half][kc][4096 words]
__device__ float g_gwp[2 * 8 * 4096];
__device__ float g_owp[2 * 8 * 4096];
// reduction scratch
__device__ float g_part1[BQ * 16 * DQ];
__device__ float g_part1m[BQ * 16];
__device__ float g_part3[BQ * 16 * HV];
__device__ float g_mx[BQ * HQ];
__device__ float g_is[BQ * HQ];

// ---------------- helpers -------------------------------------------------------
__device__ __forceinline__ unsigned f2tf(float f) {
    unsigned u;
    asm("cvt.rna.tf32.f32 %0, %1;" : "=r"(u) : "f"(f));
    return u;
}
__device__ __forceinline__ uint32_t smem_u32(const void* p) {
    uint32_t a;
    asm("{ .reg .u64 t; cvta.to.shared.u64 t, %1; cvt.u32.u64 %0, t; }" : "=r"(a) : "l"(p));
    return a;
}
__device__ __forceinline__ void cp16(uint32_t saddr, const void* g) {
    asm volatile("cp.async.cg.shared.global [%0], [%1], 16;" :: "r"(saddr), "l"(g) : "memory");
}
__device__ __forceinline__ void cp_commit() {
    asm volatile("cp.async.commit_group;" ::: "memory");
}
template <int N>
__device__ __forceinline__ void cp_wait() {
    asm volatile("cp.async.wait_group %0;" :: "n"(N) : "memory");
}
__device__ __forceinline__ void mma_tf32(float* d, const unsigned* a, const unsigned* b) {
    asm volatile(
        "mma.sync.aligned.m16n8k8.row.col.f32.tf32.tf32.f32 "
        "{%0,%1,%2,%3}, {%4,%5,%6,%7}, {%8,%9}, {%0,%1,%2,%3};\n"
        : "+f"(d[0]), "+f"(d[1]), "+f"(d[2]), "+f"(d[3])
        : "r"(a[0]), "r"(a[1]), "r"(a[2]), "r"(a[3]), "r"(b[0]), "r"(b[1]));
}

// ---------------- K0: pack weights into fragment images -------------------------
__global__ void k0_pack(const float* __restrict__ gw, const float* __restrict__ ow) {
    int idx = blockIdx.x * 256 + threadIdx.x;
    int k = idx >> 8, n = idx & 255;
    int half = n >> 7, nn = n & 127;
    int wn = nn >> 6, c = nn & 63, ni = c >> 3, gr = c & 7;
    int kc = k >> 5, r = k & 31, ks = r >> 3, rr = r & 7, tig = rr & 3, d = rr >> 2;
    int lane = gr * 4 + tig;
    size_t w = ((size_t)(half * 8 + kc)) * 4096 +
               (((ks * 2 + wn) * 32 + lane) * 16 + ni * 2 + d);
    g_gwp[w] = __uint_as_float(f2tf(gw[k * 256 + n]));
    g_owp[w] = __uint_as_float(f2tf(ow[k * 256 + n]));
}

// ---------------- K1a/K1b -------------------------------------------------------
__global__ void k1a(const float* __restrict__ qd, const float* __restrict__ qm) {
    int b = blockIdx.x, ch = blockIdx.y, t = threadIdx.x;
    __shared__ float msk[128];
    int n0 = ch * 128;
    if (t < 128) msk[t] = qm[b * NQ + n0 + t];
    __syncthreads();

    const float* base = qd + ((size_t)b * NQ + n0) * DQ + t;
    float acc = 0.f;
#pragma unroll 8
    for (int r = 0; r < 128; r++) acc += msk[r] * base[(size_t)r * DQ];
    g_part1[(b * 16 + ch) * DQ + t] = acc;

    if (t < 32) {
        float s = 0.f;
        for (int i = t; i < 128; i += 32) s += msk[i];
#pragma unroll
        for (int o = 16; o > 0; o >>= 1) s += __shfl_xor_sync(0xffffffffu, s, o);
        if (t == 0) g_part1m[b * 16 + ch] = s;
    }
}

__global__ void k1b(const float* __restrict__ qw) {
    int b = blockIdx.x, t = threadIdx.x;
    __shared__ float qavg[DQ];
    float s = 0.f, ms = 0.f;
#pragma unroll
    for (int c = 0; c < 16; c++) {
        s += g_part1[(b * 16 + c) * DQ + t];
        ms += g_part1m[b * 16 + c];
    }
    qavg[t] = s / (ms + 1e-10f);
    __syncthreads();

    float r = 0.f;
#pragma unroll 8
    for (int d = 0; d < DQ; d++) r += qavg[d] * qw[d * 256 + t];
    g_q[b * 256 + t] = r * 0.17677669529663687f;
}

// ---------------- K2: k/v via tf32 MMA + logits ---------------------------------
__global__ __launch_bounds__(256) void k2_kv_logits(const float* __restrict__ md,
                                                    const float* __restrict__ qm,
                                                    const float* __restrict__ kw,
                                                    const float* __restrict__ vw) {
    int n0 = blockIdx.x * 128;
    int b  = blockIdx.y;
    int t  = threadIdx.x;
    const int lane = t & 31, wid = t >> 5;
    const int wm = wid >> 1, wn = wid & 1;
    const int gr = lane >> 2, tig = lane & 3;

    __shared__ unsigned As[128 * 36];
    __shared__ unsigned Bs[32 * 68];
    __shared__ float qs[8][32];
    float* Asf = (float*)As;

    float acc[2][4][4];
#pragma unroll
    for (int mi = 0; mi < 2; mi++)
#pragma unroll
        for (int ni = 0; ni < 4; ni++)
#pragma unroll
            for (int j = 0; j < 4; j++) acc[mi][ni][j] = 0.f;

    const float* Abase = md + ((size_t)b * NQ + n0) * DQ;

    float4 a4[4], b4[2];
#pragma unroll
    for (int i = 0; i < 4; i++) {
        int s = t + i * 256;
        int row = s >> 3, c4 = s & 7;
        a4[i] = *(const float4*)(Abase + (size_t)row * DQ + c4 * 4);
    }
#pragma unroll
    for (int i = 0; i < 2; i++) {
        int s = t + i * 256;
        int k = s >> 4, c8 = s & 15;
        b4[i] = (c8 < 8) ? *(const float4*)(kw + k * 32 + c8 * 4)
                         : *(const float4*)(vw + k * 32 + (c8 - 8) * 4);
    }

#pragma unroll 1
    for (int kc = 0; kc < 8; kc++) {
        __syncthreads();
#pragma unroll
        for (int i = 0; i < 4; i++) {
            int s = t + i * 256;
            int row = s >> 3, c4 = s & 7;
            As[row * 36 + c4 * 4 + 0] = f2tf(a4[i].x);
            As[row * 36 + c4 * 4 + 1] = f2tf(a4[i].y);
            As[row * 36 + c4 * 4 + 2] = f2tf(a4[i].z);
            As[row * 36 + c4 * 4 + 3] = f2tf(a4[i].w);
        }
#pragma unroll
        for (int i = 0; i < 2; i++) {
            int s = t + i * 256;
            int k = s >> 4, c8 = s & 15;
            Bs[k * 68 + c8 * 4 + 0] = f2tf(b4[i].x);
            Bs[k * 68 + c8 * 4 + 1] = f2tf(b4[i].y);
            Bs[k * 68 + c8 * 4 + 2] = f2tf(b4[i].z);
            Bs[k * 68 + c8 * 4 + 3] = f2tf(b4[i].w);
        }
        __syncthreads();
        if (kc < 7) {
#pragma unroll
            for (int i = 0; i < 4; i++) {
                int s = t + i * 256;
                int row = s >> 3, c4 = s & 7;
                a4[i] = *(const float4*)(Abase + (size_t)row * DQ + (kc + 1) * 32 + c4 * 4);
            }
#pragma unroll
            for (int i = 0; i < 2; i++) {
                int s = t + i * 256;
                int k = (kc + 1) * 32 + (s >> 4);
                int c8 = s & 15;
                b4[i] = (c8 < 8) ? *(const float4*)(kw + k * 32 + c8 * 4)
                                 : *(const float4*)(vw + k * 32 + (c8 - 8) * 4);
            }
        }
#pragma unroll
        for (int ks = 0; ks < 4; ks++) {
            const int k0 = ks * 8;
            unsigned af[2][4];
#pragma unroll
            for (int mi = 0; mi < 2; mi++) {
                int rb = wm * 32 + mi * 16;
                af[mi][0] = As[(rb + gr) * 36 + k0 + tig];
                af[mi][1] = As[(rb + gr + 8) * 36 + k0 + tig];
                af[mi][2] = As[(rb + gr) * 36 + k0 + tig + 4];
                af[mi][3] = As[(rb + gr + 8) * 36 + k0 + tig + 4];
            }
            unsigned bf[4][2];
#pragma unroll
            for (int ni = 0; ni < 4; ni++) {
                int cb = wn * 32 + ni * 8 + gr;
                bf[ni][0] = Bs[(k0 + tig) * 68 + cb];
                bf[ni][1] = Bs[(k0 + tig + 4) * 68 + cb];
            }
#pragma unroll
            for (int mi = 0; mi < 2; mi++)
#pragma unroll
                for (int ni = 0; ni < 4; ni++)
                    mma_tf32(acc[mi][ni], af[mi], bf[ni]);
        }
    }

    __syncthreads();
    qs[t >> 5][t & 31] = g_q[b * 256 + t];

#pragma unroll
    for (int mi = 0; mi < 2; mi++) {
#pragma unroll
        for (int ni = 0; ni < 4; ni++) {
            int col = wn * 32 + ni * 8 + tig * 2;
#pragma unroll
            for (int half = 0; half < 2; half++) {
                int row = wm * 32 + mi * 16 + gr + half * 8;
                float x0 = acc[mi][ni][half * 2 + 0];
                float x1 = acc[mi][ni][half * 2 + 1];
                if (col < 32) {
                    Asf[row * 33 + col] = x0;
                    Asf[row * 33 + col + 1] = x1;
                } else {
                    g_v[((size_t)b * NQ + n0 + row) * VDQ + (col - 32)] = x0;
                    g_v[((size_t)b * NQ + n0 + row) * VDQ + (col - 31)] = x1;
                }
            }
        }
    }
    __syncthreads();

#pragma unroll
    for (int ii = 0; ii < 4; ii++) {
        int idx = ii * 256 + t;
        int h = idx & 7, n = idx >> 3;
        float s = 0.f;
#pragma unroll
        for (int kd = 0; kd < 32; kd++) s += qs[h][kd] * Asf[n * 33 + kd];
        float maskv = qm[b * NQ + n0 + n];
        g_logits[((size_t)b * HQ + h) * NQ + n0 + n] = s + 1e9f * (maskv - 1.0f);
    }
}

// ---------------- K3a/K3b/K3c ---------------------------------------------------
__global__ void k3a() {
    int b = blockIdx.x, h = blockIdx.y, t = threadIdx.x;
    const float* lrow = g_logits + ((size_t)b * HQ + h) * NQ;
    __shared__ float red[256];

    float m = -1e30f;
#pragma unroll
    for (int i = 0; i < 8; i++) m = fmaxf(m, lrow[t + i * 256]);
    red[t] = m;
    __syncthreads();
    for (int s = 128; s > 0; s >>= 1) {
        if (t < s) red[t] = fmaxf(red[t], red[t + s]);
        __syncthreads();
    }
    float mx = red[0];
    __syncthreads();

    float s = 0.f;
#pragma unroll
    for (int i = 0; i < 8; i++) s += __expf(lrow[t + i * 256] - mx);
    red[t] = s;
    __syncthreads();
    for (int st = 128; st > 0; st >>= 1) {
        if (t < st) red[t] += red[t + st];
        __syncthreads();
    }
    if (t == 0) {
        g_mx[b * 8 + h] = mx;
        g_is[b * 8 + h] = 1.0f / red[0];
    }
}

__global__ void k3b() {
    int b = blockIdx.x, ch = blockIdx.y, t = threadIdx.x;
    int lane = t & 31, wid = t >> 5;
    __shared__ float vsm[128][33];
    __shared__ float lgs[8][128];
    __shared__ float mxs[8];
    int n0 = ch * 128;

    if (t < 8) mxs[t] = g_mx[b * 8 + t];
#pragma unroll
    for (int i = 0; i < 16; i++) {
        int s = t + i * 256;
        int row = s >> 5, col = s & 31;
        vsm[row][col] = g_v[((size_t)b * NQ + n0 + row) * VDQ + col];
    }
#pragma unroll
    for (int i = 0; i < 4; i++) {
        int s = t + i * 256;
        int hh = s >> 7, n = s & 127;
        lgs[hh][n] = g_logits[((size_t)b * HQ + hh) * NQ + n0 + n];
    }
    __syncthreads();
#pragma unroll
    for (int i = 0; i < 4; i++) {
        int s = t + i * 256;
        int hh = s >> 7, n = s & 127;
        lgs[hh][n] = __expf(lgs[hh][n] - mxs[hh]);
    }
    __syncthreads();

    float acc = 0.f;
#pragma unroll 8
    for (int n = 0; n < 128; n++) acc += lgs[wid][n] * vsm[n][lane];
    g_part3[((b * 16 + ch) * 8 + wid) * 32 + lane] = acc;
}

__global__ void k3c() {
    int b = blockIdx.x, t = threadIdx.x;
    int h = t >> 5, vd = t & 31;
    float s = 0.f;
#pragma unroll
    for (int c = 0; c < 16; c++) s += g_part3[((b * 16 + c) * 8 + h) * 32 + vd];
    g_wavg[b * HV + t] = s * g_is[b * 8 + h];
}

// ---------------- K4: tf32 MMA, 64x64 warp tiles, 3-stage cp.async --------------
// 128 threads (4 warps, 2x2 grid). stage: A 16384 B (XOR swizzle) + B 20480 B
#define A_BYTES  16384
#define B_BYTES  20480
#define ST_BYTES 36864
#define B_BOFF   16384
#define K4_SMEM  (3 * ST_BYTES)

// EPI = 0: A raw fp32 (qd) via cp.async; f2tf at fragment load; epilogue -> image
// EPI = 1: A pre-converted image via cp.async; epilogue -> out
template <int EPI>
__global__ __launch_bounds__(128, 2) void k4_mma(const float* __restrict__ Ag,
                                                 const float* __restrict__ Bp,
                                                 const float* __restrict__ bias,
                                                 float* __restrict__ Cg) {
    extern __shared__ unsigned sm[];
    const uint32_t sb = smem_u32(sm);

    const int tile = blockIdx.x;
    const int r0 = tile * 128;
    const int chalf = blockIdx.y;
    const int c0 = chalf * 128;
    const int t = threadIdx.x;
    const int lane = t & 31, wid = t >> 5;
    const int wm = wid >> 1, wn = wid & 1;      // 2 x 2 warp grid, 64x64 tiles
    const int gr = lane >> 2, tig = lane & 3;
    const int b = r0 >> 11;

    float acc[4][8][4];
#pragma unroll
    for (int mi = 0; mi < 4; mi++)
#pragma unroll
        for (int ni = 0; ni < 8; ni++)
#pragma unroll
            for (int j = 0; j < 4; j++) acc[mi][ni][j] = 0.f;

    // ---- issue one stage's cp.async (A + B); 128 threads, 8 cp16 each ----
    auto issue_stage = [&](int kc) {
        uint32_t base = sb + (kc % 3) * ST_BYTES;
        const uint4* bsrc = (const uint4*)(Bp + (size_t)(chalf * 8 + kc) * 4096);
#pragma unroll
        for (int i = 0; i < 8; i++) {
            int q = t + i * 128;
            cp16(base + B_BOFF + (uint32_t)(q >> 2) * 80 + (q & 3) * 16, bsrc + q);
        }
        if (EPI == 0) {
#pragma unroll
            for (int i = 0; i < 8; i++) {
                int q = t + i * 128;
                int row = q >> 3, c4 = q & 7;
                cp16(base + (uint32_t)row * 128 + ((c4 ^ (row & 7)) * 16),
                     Ag + (size_t)(r0 + row) * 256 + kc * 32 + c4 * 4);
            }
        } else {
            const uint4* asrc = (const uint4*)(g_gated + (size_t)(tile * 8 + kc) * 4096);
#pragma unroll
            for (int i = 0; i < 8; i++) {
                int q = t + i * 128;
                int row = q >> 3, c4 = q & 7;
                cp16(base + (uint32_t)row * 128 + ((c4 ^ (row & 7)) * 16), asrc + q);
            }
        }
        cp_commit();
    };

    issue_stage(0);
    issue_stage(1);

#pragma unroll 1
    for (int kc = 0; kc < 8; kc++) {
        if (kc < 7) cp_wait<1>(); else cp_wait<0>();
        __syncthreads();           // stage kc visible; prior compute done
        if (kc + 2 < 8) issue_stage(kc + 2);

        const unsigned* As = sm + (kc % 3) * (ST_BYTES / 4);
        const unsigned char* Bb = (const unsigned char*)As + B_BOFF;

#pragma unroll
        for (int ks = 0; ks < 4; ks++) {
            unsigned af[4][4];
#pragma unroll
            for (int mi = 0; mi < 4; mi++) {
                int rb = wm * 64 + mi * 16;
                int r1 = rb + gr, r2 = r1 + 8;
                if (EPI == 0) {
                    unsigned v0 = As[r1 * 32 + ((ks * 2) ^ (r1 & 7)) * 4 + tig];
                    unsigned v1 = As[r2 * 32 + ((ks * 2) ^ (r2 & 7)) * 4 + tig];
                    unsigned v2 = As[r1 * 32 + ((ks * 2 + 1) ^ (r1 & 7)) * 4 + tig];
                    unsigned v3 = As[r2 * 32 + ((ks * 2 + 1) ^ (r2 & 7)) * 4 + tig];
                    af[mi][0] = f2tf(__uint_as_float(v0));
                    af[mi][1] = f2tf(__uint_as_float(v1));
                    af[mi][2] = f2tf(__uint_as_float(v2));
                    af[mi][3] = f2tf(__uint_as_float(v3));
                } else {
                    int g = ks * 2 + (tig >> 1), off = (tig & 1) * 2;
                    uint2 p0 = *(const uint2*)&As[r1 * 32 + (g ^ (r1 & 7)) * 4 + off];
                    uint2 p1 = *(const uint2*)&As[r2 * 32 + (g ^ (r2 & 7)) * 4 + off];
                    af[mi][0] = p0.x; af[mi][2] = p0.y;
                    af[mi][1] = p1.x; af[mi][3] = p1.y;
                }
            }
            const uint4* bp = (const uint4*)(Bb + (uint32_t)((ks * 2 + wn) * 32 + lane) * 80);
            uint4 q0 = bp[0], q1 = bp[1], q2 = bp[2], q3 = bp[3];
            unsigned bf[8][2];
            bf[0][0] = q0.x; bf[0][1] = q0.y; bf[1][0] = q0.z; bf[1][1] = q0.w;
            bf[2][0] = q1.x; bf[2][1] = q1.y; bf[3][0] = q1.z; bf[3][1] = q1.w;
            bf[4][0] = q2.x; bf[4][1] = q2.y; bf[5][0] = q2.z; bf[5][1] = q2.w;
            bf[6][0] = q3.x; bf[6][1] = q3.y; bf[7][0] = q3.z; bf[7][1] = q3.w;
#pragma unroll
            for (int mi = 0; mi < 4; mi++)
#pragma unroll
                for (int ni = 0; ni < 8; ni++)
                    mma_tf32(acc[mi][ni], af[mi], bf[ni]);
        }
    }

    // ---- epilogue ----
#pragma unroll
    for (int mi = 0; mi < 4; mi++) {
#pragma unroll
        for (int ni = 0; ni < 8; ni++) {
            int rowl = wm * 64 + mi * 16 + gr;
            int col = c0 + wn * 64 + ni * 8 + tig * 2;
#pragma unroll
            for (int half = 0; half < 2; half++) {
                int rl = rowl + half * 8;
                float x0 = acc[mi][ni][half * 2 + 0];
                float x1 = acc[mi][ni][half * 2 + 1];
                if (EPI == 0) {
                    float b0 = bias[col], b1 = bias[col + 1];
                    float g0 = 1.0f / (1.0f + __expf(-(x0 + b0)));
                    float g1 = 1.0f / (1.0f + __expf(-(x1 + b1)));
                    float2 w = *(const float2*)&g_wavg[b * HV + col];
                    float v0 = __uint_as_float(f2tf(g0 * w.x));
                    float v1 = __uint_as_float(f2tf(g1 * w.y));
                    int kcc = col >> 5, cc = col & 31, gg = cc >> 3, ww = cc & 7;
                    int w0p = (ww & 3) * 2 + (ww >> 2);
                    int w1p = ((ww + 1) & 3) * 2 + ((ww + 1) >> 2);
                    size_t base = ((size_t)(tile * 8 + kcc) * 128 + rl) * 32 + gg * 8;
                    g_gated[base + w0p] = v0;
                    g_gated[base + w1p] = v1;
                } else {
                    float2 o;
                    o.x = x0 + bias[col];
                    o.y = x1 + bias[col + 1];
                    *(float2*)&Cg[(size_t)(r0 + rl) * 256 + col] = o;
                }
            }
        }
    }
}

// ---------------- launcher ------------------------------------------------------
extern "C" void kernel_launch(void* const* d_in, const int* in_sizes, int n_in,
                              void* d_out, int out_size) {
    const float* qd = (const float*)d_in[0];
    const float* md = (const float*)d_in[1];
    const float* qm = (const float*)d_in[2];
    const float* qw = (const float*)d_in[3];
    const float* kw = (const float*)d_in[4];
    const float* vw = (const float*)d_in[5];
    const float* gw = (const float*)d_in[6];
    const float* gb = (const float*)d_in[7];
    const float* ow = (const float*)d_in[8];
    const float* ob = (const float*)d_in[9];
    float* out = (float*)d_out;

    float *gwp = nullptr, *owp = nullptr;
    cudaGetSymbolAddress((void**)&gwp, g_gwp);
    cudaGetSymbolAddress((void**)&owp, g_owp);

    cudaFuncSetAttribute(k4_mma<0>, cudaFuncAttributeMaxDynamicSharedMemorySize, K4_SMEM);
    cudaFuncSetAttribute(k4_mma<1>, cudaFuncAttributeMaxDynamicSharedMemorySize, K4_SMEM);

    k0_pack<<<256, 256>>>(gw, ow);
    k1a<<<dim3(BQ, 16), 256>>>(qd, qm);
    k1b<<<BQ, 256>>>(qw);
    k2_kv_logits<<<dim3(NQ / 128, BQ), 256>>>(md, qm, kw, vw);
    k3a<<<dim3(BQ, HQ), 256>>>();
    k3b<<<dim3(BQ, 16), 256>>>();
    k3c<<<BQ, 256>>>();
    k4_mma<0><<<dim3((BQ * NQ) / 128, HV / 128), 128, K4_SMEM>>>(qd, gwp, gb, nullptr);
    k4_mma<1><<<dim3((BQ * NQ) / 128, OQ / 128), 128, K4_SMEM>>>(nullptr, owp, ob, out);
}

// round 12
// speedup vs baseline: 1.0526x; 1.0526x over previous
#include <cuda_runtime.h>
#include <math.h>
#include <stdint.h>

#define BQ 64
#define NQ 2048
#define DQ 256
#define HQ 8
#define KDQ 32
#define VDQ 32
#define OQ 256
#define HV 256

// ---------------- scratch (static device arrays: no allocation) ----------------
__device__ float g_q[BQ * HQ * KDQ];
__device__ float g_v[(size_t)BQ * NQ * VDQ];
__device__ float g_logits[(size_t)BQ * HQ * NQ];
__device__ float g_wavg[BQ * HV];
// g_gated: per (tile, kc) fragment-image: [1024][8][128 rows][32 words]
__device__ float g_gated[(size_t)1024 * 8 * 4096];   // 128 MB
// packed B weight images: [half][kc][4096 words]
__device__ float g_gwp[2 * 8 * 4096];
__device__ float g_owp[2 * 8 * 4096];
// reduction scratch
__device__ float g_part1[BQ * 16 * DQ];
__device__ float g_part1m[BQ * 16];
__device__ float g_part3[BQ * 16 * HV];
__device__ float g_mx[BQ * HQ];
__device__ float g_is[BQ * HQ];

// ---------------- helpers -------------------------------------------------------
__device__ __forceinline__ unsigned f2tf(float f) {
    unsigned u;
    asm("cvt.rna.tf32.f32 %0, %1;" : "=r"(u) : "f"(f));
    return u;
}
__device__ __forceinline__ uint32_t smem_u32(const void* p) {
    uint32_t a;
    asm("{ .reg .u64 t; cvta.to.shared.u64 t, %1; cvt.u32.u64 %0, t; }" : "=r"(a) : "l"(p));
    return a;
}
__device__ __forceinline__ void cp16(uint32_t saddr, const void* g) {
    asm volatile("cp.async.cg.shared.global [%0], [%1], 16;" :: "r"(saddr), "l"(g) : "memory");
}
__device__ __forceinline__ void cp_commit() {
    asm volatile("cp.async.commit_group;" ::: "memory");
}
template <int N>
__device__ __forceinline__ void cp_wait() {
    asm volatile("cp.async.wait_group %0;" :: "n"(N) : "memory");
}
__device__ __forceinline__ void mma_tf32(float* d, const unsigned* a, const unsigned* b) {
    asm volatile(
        "mma.sync.aligned.m16n8k8.row.col.f32.tf32.tf32.f32 "
        "{%0,%1,%2,%3}, {%4,%5,%6,%7}, {%8,%9}, {%0,%1,%2,%3};\n"
        : "+f"(d[0]), "+f"(d[1]), "+f"(d[2]), "+f"(d[3])
        : "r"(a[0]), "r"(a[1]), "r"(a[2]), "r"(a[3]), "r"(b[0]), "r"(b[1]));
}

// ---------------- K0: pack weights into fragment images -------------------------
__global__ void k0_pack(const float* __restrict__ gw, const float* __restrict__ ow) {
    int idx = blockIdx.x * 256 + threadIdx.x;
    int k = idx >> 8, n = idx & 255;
    int half = n >> 7, nn = n & 127;
    int wn = nn >> 6, c = nn & 63, ni = c >> 3, gr = c & 7;
    int kc = k >> 5, r = k & 31, ks = r >> 3, rr = r & 7, tig = rr & 3, d = rr >> 2;
    int lane = gr * 4 + tig;
    size_t w = ((size_t)(half * 8 + kc)) * 4096 +
               (((ks * 2 + wn) * 32 + lane) * 16 + ni * 2 + d);
    g_gwp[w] = __uint_as_float(f2tf(gw[k * 256 + n]));
    g_owp[w] = __uint_as_float(f2tf(ow[k * 256 + n]));
}

// ---------------- K1a/K1b -------------------------------------------------------
__global__ void k1a(const float* __restrict__ qd, const float* __restrict__ qm) {
    int b = blockIdx.x, ch = blockIdx.y, t = threadIdx.x;
    __shared__ float msk[128];
    int n0 = ch * 128;
    if (t < 128) msk[t] = qm[b * NQ + n0 + t];
    __syncthreads();

    const float* base = qd + ((size_t)b * NQ + n0) * DQ + t;
    float acc = 0.f;
#pragma unroll 8
    for (int r = 0; r < 128; r++) acc += msk[r] * base[(size_t)r * DQ];
    g_part1[(b * 16 + ch) * DQ + t] = acc;

    if (t < 32) {
        float s = 0.f;
        for (int i = t; i < 128; i += 32) s += msk[i];
#pragma unroll
        for (int o = 16; o > 0; o >>= 1) s += __shfl_xor_sync(0xffffffffu, s, o);
        if (t == 0) g_part1m[b * 16 + ch] = s;
    }
}

__global__ void k1b(const float* __restrict__ qw) {
    int b = blockIdx.x, t = threadIdx.x;
    __shared__ float qavg[DQ];
    float s = 0.f, ms = 0.f;
#pragma unroll
    for (int c = 0; c < 16; c++) {
        s += g_part1[(b * 16 + c) * DQ + t];
        ms += g_part1m[b * 16 + c];
    }
    qavg[t] = s / (ms + 1e-10f);
    __syncthreads();

    float r = 0.f;
#pragma unroll 8
    for (int d = 0; d < DQ; d++) r += qavg[d] * qw[d * 256 + t];
    g_q[b * 256 + t] = r * 0.17677669529663687f;
}

// ---------------- K2: k/v via tf32 MMA + logits (3-stage cp.async A) ------------
#define K2_ST  16384
#define K2_SMEM (3 * K2_ST)

__global__ __launch_bounds__(256) void k2_kv_logits(const float* __restrict__ md,
                                                    const float* __restrict__ qm,
                                                    const float* __restrict__ kw,
                                                    const float* __restrict__ vw) {
    extern __shared__ unsigned dsm[];
    const uint32_t sb = smem_u32(dsm);

    int n0 = blockIdx.x * 128;
    int b  = blockIdx.y;
    int t  = threadIdx.x;
    const int lane = t & 31, wid = t >> 5;
    const int wm = wid >> 1, wn = wid & 1;
    const int gr = lane >> 2, tig = lane & 3;

    __shared__ unsigned Bs[32 * 68];
    __shared__ float qs[8][32];

    float acc[2][4][4];
#pragma unroll
    for (int mi = 0; mi < 2; mi++)
#pragma unroll
        for (int ni = 0; ni < 4; ni++)
#pragma unroll
            for (int j = 0; j < 4; j++) acc[mi][ni][j] = 0.f;

    const float* Abase = md + ((size_t)b * NQ + n0) * DQ;

    auto issue_a = [&](int kc) {
        uint32_t base = sb + (kc % 3) * K2_ST;
#pragma unroll
        for (int i = 0; i < 4; i++) {
            int q = t + i * 256;
            int row = q >> 3, c4 = q & 7;
            cp16(base + (uint32_t)row * 128 + ((c4 ^ (row & 7)) * 16),
                 Abase + (size_t)row * DQ + kc * 32 + c4 * 4);
        }
        cp_commit();
    };

    float4 b4[2];
#pragma unroll
    for (int i = 0; i < 2; i++) {
        int s = t + i * 256;
        int k = s >> 4, c8 = s & 15;
        b4[i] = (c8 < 8) ? *(const float4*)(kw + k * 32 + c8 * 4)
                         : *(const float4*)(vw + k * 32 + (c8 - 8) * 4);
    }
    issue_a(0);
    issue_a(1);

#pragma unroll 1
    for (int kc = 0; kc < 8; kc++) {
        __syncthreads();   // previous compute done; Bs free
#pragma unroll
        for (int i = 0; i < 2; i++) {
            int s = t + i * 256;
            int k = s >> 4, c8 = s & 15;
            Bs[k * 68 + c8 * 4 + 0] = f2tf(b4[i].x);
            Bs[k * 68 + c8 * 4 + 1] = f2tf(b4[i].y);
            Bs[k * 68 + c8 * 4 + 2] = f2tf(b4[i].z);
            Bs[k * 68 + c8 * 4 + 3] = f2tf(b4[i].w);
        }
        if (kc < 7) cp_wait<1>(); else cp_wait<0>();
        __syncthreads();   // Bs written + A stage kc visible
        if (kc + 2 < 8) issue_a(kc + 2);
        if (kc < 7) {
#pragma unroll
            for (int i = 0; i < 2; i++) {
                int s = t + i * 256;
                int k = (kc + 1) * 32 + (s >> 4);
                int c8 = s & 15;
                b4[i] = (c8 < 8) ? *(const float4*)(kw + k * 32 + c8 * 4)
                                 : *(const float4*)(vw + k * 32 + (c8 - 8) * 4);
            }
        }

        const unsigned* As = dsm + (kc % 3) * (K2_ST / 4);
#pragma unroll
        for (int ks = 0; ks < 4; ks++) {
            const int k0 = ks * 8;
            unsigned af[2][4];
#pragma unroll
            for (int mi = 0; mi < 2; mi++) {
                int rb = wm * 32 + mi * 16;
                int r1 = rb + gr, r2 = r1 + 8;
                unsigned v0 = As[r1 * 32 + ((ks * 2) ^ (r1 & 7)) * 4 + tig];
                unsigned v1 = As[r2 * 32 + ((ks * 2) ^ (r2 & 7)) * 4 + tig];
                unsigned v2 = As[r1 * 32 + ((ks * 2 + 1) ^ (r1 & 7)) * 4 + tig];
                unsigned v3 = As[r2 * 32 + ((ks * 2 + 1) ^ (r2 & 7)) * 4 + tig];
                af[mi][0] = f2tf(__uint_as_float(v0));
                af[mi][1] = f2tf(__uint_as_float(v1));
                af[mi][2] = f2tf(__uint_as_float(v2));
                af[mi][3] = f2tf(__uint_as_float(v3));
            }
            unsigned bf[4][2];
#pragma unroll
            for (int ni = 0; ni < 4; ni++) {
                int cb = wn * 32 + ni * 8 + gr;
                bf[ni][0] = Bs[(k0 + tig) * 68 + cb];
                bf[ni][1] = Bs[(k0 + tig + 4) * 68 + cb];
            }
#pragma unroll
            for (int mi = 0; mi < 2; mi++)
#pragma unroll
                for (int ni = 0; ni < 4; ni++)
                    mma_tf32(acc[mi][ni], af[mi], bf[ni]);
        }
    }

    __syncthreads();   // all A-stage reads done; reuse dsm as float k-storage
    float* Asf = (float*)dsm;
    qs[t >> 5][t & 31] = g_q[b * 256 + t];

#pragma unroll
    for (int mi = 0; mi < 2; mi++) {
#pragma unroll
        for (int ni = 0; ni < 4; ni++) {
            int col = wn * 32 + ni * 8 + tig * 2;
#pragma unroll
            for (int half = 0; half < 2; half++) {
                int row = wm * 32 + mi * 16 + gr + half * 8;
                float x0 = acc[mi][ni][half * 2 + 0];
                float x1 = acc[mi][ni][half * 2 + 1];
                if (col < 32) {
                    Asf[row * 33 + col] = x0;
                    Asf[row * 33 + col + 1] = x1;
                } else {
                    g_v[((size_t)b * NQ + n0 + row) * VDQ + (col - 32)] = x0;
                    g_v[((size_t)b * NQ + n0 + row) * VDQ + (col - 31)] = x1;
                }
            }
        }
    }
    __syncthreads();

#pragma unroll
    for (int ii = 0; ii < 4; ii++) {
        int idx = ii * 256 + t;
        int h = idx & 7, n = idx >> 3;
        float s = 0.f;
#pragma unroll
        for (int kd = 0; kd < 32; kd++) s += qs[h][kd] * Asf[n * 33 + kd];
        float maskv = qm[b * NQ + n0 + n];
        g_logits[((size_t)b * HQ + h) * NQ + n0 + n] = s + 1e9f * (maskv - 1.0f);
    }
}

// ---------------- K3a/K3b/K3c ---------------------------------------------------
__global__ void k3a() {
    int b = blockIdx.x, h = blockIdx.y, t = threadIdx.x;
    const float* lrow = g_logits + ((size_t)b * HQ + h) * NQ;
    __shared__ float red[256];

    float m = -1e30f;
#pragma unroll
    for (int i = 0; i < 8; i++) m = fmaxf(m, lrow[t + i * 256]);
    red[t] = m;
    __syncthreads();
    for (int s = 128; s > 0; s >>= 1) {
        if (t < s) red[t] = fmaxf(red[t], red[t + s]);
        __syncthreads();
    }
    float mx = red[0];
    __syncthreads();

    float s = 0.f;
#pragma unroll
    for (int i = 0; i < 8; i++) s += __expf(lrow[t + i * 256] - mx);
    red[t] = s;
    __syncthreads();
    for (int st = 128; st > 0; st >>= 1) {
        if (t < st) red[t] += red[t + st];
        __syncthreads();
    }
    if (t == 0) {
        g_mx[b * 8 + h] = mx;
        g_is[b * 8 + h] = 1.0f / red[0];
    }
}

__global__ void k3b() {
    int b = blockIdx.x, ch = blockIdx.y, t = threadIdx.x;
    int lane = t & 31, wid = t >> 5;
    __shared__ float vsm[128][33];
    __shared__ float lgs[8][128];
    __shared__ float mxs[8];
    int n0 = ch * 128;

    if (t < 8) mxs[t] = g_mx[b * 8 + t];
#pragma unroll
    for (int i = 0; i < 16; i++) {
        int s = t + i * 256;
        int row = s >> 5, col = s & 31;
        vsm[row][col] = g_v[((size_t)b * NQ + n0 + row) * VDQ + col];
    }
#pragma unroll
    for (int i = 0; i < 4; i++) {
        int s = t + i * 256;
        int hh = s >> 7, n = s & 127;
        lgs[hh][n] = g_logits[((size_t)b * HQ + hh) * NQ + n0 + n];
    }
    __syncthreads();
#pragma unroll
    for (int i = 0; i < 4; i++) {
        int s = t + i * 256;
        int hh = s >> 7, n = s & 127;
        lgs[hh][n] = __expf(lgs[hh][n] - mxs[hh]);
    }
    __syncthreads();

    float acc = 0.f;
#pragma unroll 8
    for (int n = 0; n < 128; n++) acc += lgs[wid][n] * vsm[n][lane];
    g_part3[((b * 16 + ch) * 8 + wid) * 32 + lane] = acc;
}

__global__ void k3c() {
    int b = blockIdx.x, t = threadIdx.x;
    int h = t >> 5, vd = t & 31;
    float s = 0.f;
#pragma unroll
    for (int c = 0; c < 16; c++) s += g_part3[((b * 16 + c) * 8 + h) * 32 + vd];
    g_wavg[b * HV + t] = s * g_is[b * 8 + h];
}

// ---------------- K4: tf32 MMA, 3-stage cp.async, XOR-swizzled A (R10 config) ---
#define A_BYTES  16384
#define B_BYTES  20480
#define ST_BYTES 36864
#define B_BOFF   16384
#define K4_SMEM  (3 * ST_BYTES)

template <int EPI>
__global__ __launch_bounds__(256, 2) void k4_mma(const float* __restrict__ Ag,
                                                 const float* __restrict__ Bp,
                                                 const float* __restrict__ bias,
                                                 float* __restrict__ Cg) {
    extern __shared__ unsigned sm[];
    const uint32_t sb = smem_u32(sm);

    const int tile = blockIdx.x;
    const int r0 = tile * 128;
    const int chalf = blockIdx.y;
    const int c0 = chalf * 128;
    const int t = threadIdx.x;
    const int lane = t & 31, wid = t >> 5;
    const int wm = wid >> 1, wn = wid & 1;
    const int gr = lane >> 2, tig = lane & 3;
    const int b = r0 >> 11;

    float acc[2][8][4];
#pragma unroll
    for (int mi = 0; mi < 2; mi++)
#pragma unroll
        for (int ni = 0; ni < 8; ni++)
#pragma unroll
            for (int j = 0; j < 4; j++) acc[mi][ni][j] = 0.f;

    auto issue_stage = [&](int kc) {
        uint32_t base = sb + (kc % 3) * ST_BYTES;
        const uint4* bsrc = (const uint4*)(Bp + (size_t)(chalf * 8 + kc) * 4096);
#pragma unroll
        for (int i = 0; i < 4; i++) {
            int q = t + i * 256;
            cp16(base + B_BOFF + (uint32_t)(q >> 2) * 80 + (q & 3) * 16, bsrc + q);
        }
        if (EPI == 0) {
#pragma unroll
            for (int i = 0; i < 4; i++) {
                int q = t + i * 256;
                int row = q >> 3, c4 = q & 7;
                cp16(base + (uint32_t)row * 128 + ((c4 ^ (row & 7)) * 16),
                     Ag + (size_t)(r0 + row) * 256 + kc * 32 + c4 * 4);
            }
        } else {
            const uint4* asrc = (const uint4*)(g_gated + (size_t)(tile * 8 + kc) * 4096);
#pragma unroll
            for (int i = 0; i < 4; i++) {
                int q = t + i * 256;
                int row = q >> 3, c4 = q & 7;
                cp16(base + (uint32_t)row * 128 + ((c4 ^ (row & 7)) * 16), asrc + q);
            }
        }
        cp_commit();
    };

    issue_stage(0);
    issue_stage(1);

#pragma unroll 1
    for (int kc = 0; kc < 8; kc++) {
        if (kc < 7) cp_wait<1>(); else cp_wait<0>();
        __syncthreads();
        if (kc + 2 < 8) issue_stage(kc + 2);

        const unsigned* As = sm + (kc % 3) * (ST_BYTES / 4);
        const unsigned char* Bb = (const unsigned char*)As + B_BOFF;

#pragma unroll
        for (int ks = 0; ks < 4; ks++) {
            unsigned af[2][4];
#pragma unroll
            for (int mi = 0; mi < 2; mi++) {
                int rb = wm * 32 + mi * 16;
                if (EPI == 0) {
                    int r1 = rb + gr, r2 = rb + gr + 8;
                    unsigned v0 = As[r1 * 32 + ((ks * 2) ^ (r1 & 7)) * 4 + tig];
                    unsigned v1 = As[r2 * 32 + ((ks * 2) ^ (r2 & 7)) * 4 + tig];
                    unsigned v2 = As[r1 * 32 + ((ks * 2 + 1) ^ (r1 & 7)) * 4 + tig];
                    unsigned v3 = As[r2 * 32 + ((ks * 2 + 1) ^ (r2 & 7)) * 4 + tig];
                    af[mi][0] = f2tf(__uint_as_float(v0));
                    af[mi][1] = f2tf(__uint_as_float(v1));
                    af[mi][2] = f2tf(__uint_as_float(v2));
                    af[mi][3] = f2tf(__uint_as_float(v3));
                } else {
                    int r1 = rb + gr, r2 = rb + gr + 8;
                    int g = ks * 2 + (tig >> 1), off = (tig & 1) * 2;
                    uint2 p0 = *(const uint2*)&As[r1 * 32 + (g ^ (r1 & 7)) * 4 + off];
                    uint2 p1 = *(const uint2*)&As[r2 * 32 + (g ^ (r2 & 7)) * 4 + off];
                    af[mi][0] = p0.x; af[mi][2] = p0.y;
                    af[mi][1] = p1.x; af[mi][3] = p1.y;
                }
            }
            const uint4* bp = (const uint4*)(Bb + (uint32_t)((ks * 2 + wn) * 32 + lane) * 80);
            uint4 q0 = bp[0], q1 = bp[1], q2 = bp[2], q3 = bp[3];
            unsigned bf[8][2];
            bf[0][0] = q0.x; bf[0][1] = q0.y; bf[1][0] = q0.z; bf[1][1] = q0.w;
            bf[2][0] = q1.x; bf[2][1] = q1.y; bf[3][0] = q1.z; bf[3][1] = q1.w;
            bf[4][0] = q2.x; bf[4][1] = q2.y; bf[5][0] = q2.z; bf[5][1] = q2.w;
            bf[6][0] = q3.x; bf[6][1] = q3.y; bf[7][0] = q3.z; bf[7][1] = q3.w;
#pragma unroll
            for (int mi = 0; mi < 2; mi++)
#pragma unroll
                for (int ni = 0; ni < 8; ni++)
                    mma_tf32(acc[mi][ni], af[mi], bf[ni]);
        }
    }

    // ---- epilogue ----
#pragma unroll
    for (int mi = 0; mi < 2; mi++) {
#pragma unroll
        for (int ni = 0; ni < 8; ni++) {
            int rowl = wm * 32 + mi * 16 + gr;
            int col = c0 + wn * 64 + ni * 8 + tig * 2;
#pragma unroll
            for (int half = 0; half < 2; half++) {
                int rl = rowl + half * 8;
                float x0 = acc[mi][ni][half * 2 + 0];
                float x1 = acc[mi][ni][half * 2 + 1];
                if (EPI == 0) {
                    float b0 = bias[col], b1 = bias[col + 1];
                    float g0 = 1.0f / (1.0f + __expf(-(x0 + b0)));
                    float g1 = 1.0f / (1.0f + __expf(-(x1 + b1)));
                    float2 w = *(const float2*)&g_wavg[b * HV + col];
                    float v0 = __uint_as_float(f2tf(g0 * w.x));
                    float v1 = __uint_as_float(f2tf(g1 * w.y));
                    int kcc = col >> 5, cc = col & 31, gg = cc >> 3, ww = cc & 7;
                    int w0p = (ww & 3) * 2 + (ww >> 2);
                    int w1p = ((ww + 1) & 3) * 2 + ((ww + 1) >> 2);
                    size_t base = ((size_t)(tile * 8 + kcc) * 128 + rl) * 32 + gg * 8;
                    g_gated[base + w0p] = v0;
                    g_gated[base + w1p] = v1;
                } else {
                    float2 o;
                    o.x = x0 + bias[col];
                    o.y = x1 + bias[col + 1];
                    *(float2*)&Cg[(size_t)(r0 + rl) * 256 + col] = o;
                }
            }
        }
    }
}

// ---------------- launcher ------------------------------------------------------
extern "C" void kernel_launch(void* const* d_in, const int* in_sizes, int n_in,
                              void* d_out, int out_size) {
    const float* qd = (const float*)d_in[0];
    const float* md = (const float*)d_in[1];
    const float* qm = (const float*)d_in[2];
    const float* qw = (const float*)d_in[3];
    const float* kw = (const float*)d_in[4];
    const float* vw = (const float*)d_in[5];
    const float* gw = (const float*)d_in[6];
    const float* gb = (const float*)d_in[7];
    const float* ow = (const float*)d_in[8];
    const float* ob = (const float*)d_in[9];
    float* out = (float*)d_out;

    float *gwp = nullptr, *owp = nullptr;
    cudaGetSymbolAddress((void**)&gwp, g_gwp);
    cudaGetSymbolAddress((void**)&owp, g_owp);

    cudaFuncSetAttribute(k2_kv_logits, cudaFuncAttributeMaxDynamicSharedMemorySize, K2_SMEM);
    cudaFuncSetAttribute(k4_mma<0>, cudaFuncAttributeMaxDynamicSharedMemorySize, K4_SMEM);
    cudaFuncSetAttribute(k4_mma<1>, cudaFuncAttributeMaxDynamicSharedMemorySize, K4_SMEM);

    k0_pack<<<256, 256>>>(gw, ow);
    k1a<<<dim3(BQ, 16), 256>>>(qd, qm);
    k1b<<<BQ, 256>>>(qw);
    k2_kv_logits<<<dim3(NQ / 128, BQ), 256, K2_SMEM>>>(md, qm, kw, vw);
    k3a<<<dim3(BQ, HQ), 256>>>();
    k3b<<<dim3(BQ, 16), 256>>>();
    k3c<<<BQ, 256>>>();
    k4_mma<0><<<dim3((BQ * NQ) / 128, HV / 128), 256, K4_SMEM>>>(qd, gwp, gb, nullptr);
    k4_mma<1><<<dim3((BQ * NQ) / 128, OQ / 128), 256, K4_SMEM>>>(nullptr, owp, ob, out);
}

// round 16
// speedup vs baseline: 1.3557x; 1.2879x over previous
#include <cuda_runtime.h>
#include <cuda_fp16.h>
#include <math.h>
#include <stdint.h>

#define BQ 64
#define NQ 2048
#define DQ 256
#define HQ 8
#define KDQ 32
#define VDQ 32
#define OQ 256
#define HV 256

// ---------------- scratch (static device arrays: no allocation) ----------------
__device__ float g_q[BQ * HQ * KDQ];
__device__ float g_v[(size_t)BQ * NQ * VDQ];
__device__ float g_logits[(size_t)BQ * HQ * NQ];
__device__ float g_wavg[BQ * HV];
// gated as fp16 fragment image: per (tile,kc): 128 rows x 16 words (half2)
__device__ unsigned g_gated16[(size_t)1024 * 8 * 2048];   // 64 MB
// packed fp16 B weight images: [half][kc][2048 words]
__device__ unsigned g_gwp16[2 * 8 * 2048];
__device__ unsigned g_owp16[2 * 8 * 2048];
// reduction scratch
__device__ float g_part1[BQ * 16 * DQ];
__device__ float g_part1m[BQ * 16];
__device__ float g_part3[BQ * 16 * HV];
__device__ float g_mx[BQ * HQ];
__device__ float g_is[BQ * HQ];

// ---------------- helpers -------------------------------------------------------
__device__ __forceinline__ unsigned f2tf(float f) {
    unsigned u;
    asm("cvt.rna.tf32.f32 %0, %1;" : "=r"(u) : "f"(f));
    return u;
}
__device__ __forceinline__ uint32_t smem_u32(const void* p) {
    uint32_t a;
    asm("{ .reg .u64 t; cvta.to.shared.u64 t, %1; cvt.u32.u64 %0, t; }" : "=r"(a) : "l"(p));
    return a;
}
__device__ __forceinline__ void cp16(uint32_t saddr, const void* g) {
    asm volatile("cp.async.cg.shared.global [%0], [%1], 16;" :: "r"(saddr), "l"(g) : "memory");
}
__device__ __forceinline__ void cp_commit() {
    asm volatile("cp.async.commit_group;" ::: "memory");
}
template <int N>
__device__ __forceinline__ void cp_wait() {
    asm volatile("cp.async.wait_group %0;" :: "n"(N) : "memory");
}
__device__ __forceinline__ void mma_tf32(float* d, const unsigned* a, const unsigned* b) {
    asm volatile(
        "mma.sync.aligned.m16n8k8.row.col.f32.tf32.tf32.f32 "
        "{%0,%1,%2,%3}, {%4,%5,%6,%7}, {%8,%9}, {%0,%1,%2,%3};\n"
        : "+f"(d[0]), "+f"(d[1]), "+f"(d[2]), "+f"(d[3])
        : "r"(a[0]), "r"(a[1]), "r"(a[2]), "r"(a[3]), "r"(b[0]), "r"(b[1]));
}
__device__ __forceinline__ void mma_f16(float* d, const unsigned* a, const unsigned* b) {
    asm volatile(
        "mma.sync.aligned.m16n8k16.row.col.f32.f16.f16.f32 "
        "{%0,%1,%2,%3}, {%4,%5,%6,%7}, {%8,%9}, {%0,%1,%2,%3};\n"
        : "+f"(d[0]), "+f"(d[1]), "+f"(d[2]), "+f"(d[3])
        : "r"(a[0]), "r"(a[1]), "r"(a[2]), "r"(a[3]), "r"(b[0]), "r"(b[1]));
}
__device__ __forceinline__ unsigned pack_h2(float x, float y) {
    __half2 h = __floats2half2_rn(x, y);
    return *(unsigned*)&h;
}

// ---------------- K0: pack weights into fp16 fragment images --------------------
__global__ void k0_pack16(const float* __restrict__ gw, const float* __restrict__ ow) {
    int idx = blockIdx.x * 256 + threadIdx.x;   // 65536 (k,n)
    int k = idx >> 8, n = idx & 255;
    int himg = n >> 7, nn = n & 127;
    int wn = nn >> 6, c = nn & 63, ni = c >> 3, gr = c & 7;
    int kc = k >> 5, kk = k & 31, ks16 = kk >> 4, kr = kk & 15;
    int r = kr >> 3, pos = kr & 7, tig = pos >> 1, d = pos & 1;
    int lane = gr * 4 + tig;
    int block = (ks16 * 2 + wn) * 32 + lane;
    size_t word = ((size_t)(himg * 8 + kc)) * 2048 + block * 16 + ni * 2 + r;
    ((unsigned short*)g_gwp16)[word * 2 + d] = __half_as_ushort(__float2half_rn(gw[k * 256 + n]));
    ((unsigned short*)g_owp16)[word * 2 + d] = __half_as_ushort(__float2half_rn(ow[k * 256 + n]));
}

// ---------------- K1a/K1b -------------------------------------------------------
__global__ void k1a(const float* __restrict__ qd, const float* __restrict__ qm) {
    int b = blockIdx.x, ch = blockIdx.y, t = threadIdx.x;
    __shared__ float msk[128];
    int n0 = ch * 128;
    if (t < 128) msk[t] = qm[b * NQ + n0 + t];
    __syncthreads();

    const float* base = qd + ((size_t)b * NQ + n0) * DQ + t;
    float acc = 0.f;
#pragma unroll 8
    for (int r = 0; r < 128; r++) acc += msk[r] * base[(size_t)r * DQ];
    g_part1[(b * 16 + ch) * DQ + t] = acc;

    if (t < 32) {
        float s = 0.f;
        for (int i = t; i < 128; i += 32) s += msk[i];
#pragma unroll
        for (int o = 16; o > 0; o >>= 1) s += __shfl_xor_sync(0xffffffffu, s, o);
        if (t == 0) g_part1m[b * 16 + ch] = s;
    }
}

__global__ void k1b(const float* __restrict__ qw) {
    int b = blockIdx.x, t = threadIdx.x;
    __shared__ float qavg[DQ];
    float s = 0.f, ms = 0.f;
#pragma unroll
    for (int c = 0; c < 16; c++) {
        s += g_part1[(b * 16 + c) * DQ + t];
        ms += g_part1m[b * 16 + c];
    }
    qavg[t] = s / (ms + 1e-10f);
    __syncthreads();

    float r = 0.f;
#pragma unroll 8
    for (int d = 0; d < DQ; d++) r += qavg[d] * qw[d * 256 + t];
    g_q[b * 256 + t] = r * 0.17677669529663687f;
}

// ---------------- K2: k/v via tf32 MMA + logits (3-stage cp.async A) ------------
#define K2_ST  16384
#define K2_SMEM (3 * K2_ST)

__global__ __launch_bounds__(256) void k2_kv_logits(const float* __restrict__ md,
                                                    const float* __restrict__ qm,
                                                    const float* __restrict__ kw,
                                                    const float* __restrict__ vw) {
    extern __shared__ unsigned dsm[];
    const uint32_t sb = smem_u32(dsm);

    int n0 = blockIdx.x * 128;
    int b  = blockIdx.y;
    int t  = threadIdx.x;
    const int lane = t & 31, wid = t >> 5;
    const int wm = wid >> 1, wn = wid & 1;
    const int gr = lane >> 2, tig = lane & 3;

    __shared__ unsigned Bs[32 * 68];
    __shared__ float qs[8][32];

    float acc[2][4][4];
#pragma unroll
    for (int mi = 0; mi < 2; mi++)
#pragma unroll
        for (int ni = 0; ni < 4; ni++)
#pragma unroll
            for (int j = 0; j < 4; j++) acc[mi][ni][j] = 0.f;

    const float* Abase = md + ((size_t)b * NQ + n0) * DQ;

    auto issue_a = [&](int kc) {
        uint32_t base = sb + (kc % 3) * K2_ST;
#pragma unroll
        for (int i = 0; i < 4; i++) {
            int q = t + i * 256;
            int row = q >> 3, c4 = q & 7;
            cp16(base + (uint32_t)row * 128 + ((c4 ^ (row & 7)) * 16),
                 Abase + (size_t)row * DQ + kc * 32 + c4 * 4);
        }
        cp_commit();
    };

    float4 b4[2];
#pragma unroll
    for (int i = 0; i < 2; i++) {
        int s = t + i * 256;
        int k = s >> 4, c8 = s & 15;
        b4[i] = (c8 < 8) ? *(const float4*)(kw + k * 32 + c8 * 4)
                         : *(const float4*)(vw + k * 32 + (c8 - 8) * 4);
    }
    issue_a(0);
    issue_a(1);

#pragma unroll 1
    for (int kc = 0; kc < 8; kc++) {
        __syncthreads();
#pragma unroll
        for (int i = 0; i < 2; i++) {
            int s = t + i * 256;
            int k = s >> 4, c8 = s & 15;
            Bs[k * 68 + c8 * 4 + 0] = f2tf(b4[i].x);
            Bs[k * 68 + c8 * 4 + 1] = f2tf(b4[i].y);
            Bs[k * 68 + c8 * 4 + 2] = f2tf(b4[i].z);
            Bs[k * 68 + c8 * 4 + 3] = f2tf(b4[i].w);
        }
        if (kc < 7) cp_wait<1>(); else cp_wait<0>();
        __syncthreads();
        if (kc + 2 < 8) issue_a(kc + 2);
        if (kc < 7) {
#pragma unroll
            for (int i = 0; i < 2; i++) {
                int s = t + i * 256;
                int k = (kc + 1) * 32 + (s >> 4);
                int c8 = s & 15;
                b4[i] = (c8 < 8) ? *(const float4*)(kw + k * 32 + c8 * 4)
                                 : *(const float4*)(vw + k * 32 + (c8 - 8) * 4);
            }
        }

        const unsigned* As = dsm + (kc % 3) * (K2_ST / 4);
#pragma unroll
        for (int ks = 0; ks < 4; ks++) {
            const int k0 = ks * 8;
            unsigned af[2][4];
#pragma unroll
            for (int mi = 0; mi < 2; mi++) {
                int rb = wm * 32 + mi * 16;
                int r1 = rb + gr, r2 = r1 + 8;
                unsigned v0 = As[r1 * 32 + ((ks * 2) ^ (r1 & 7)) * 4 + tig];
                unsigned v1 = As[r2 * 32 + ((ks * 2) ^ (r2 & 7)) * 4 + tig];
                unsigned v2 = As[r1 * 32 + ((ks * 2 + 1) ^ (r1 & 7)) * 4 + tig];
                unsigned v3 = As[r2 * 32 + ((ks * 2 + 1) ^ (r2 & 7)) * 4 + tig];
                af[mi][0] = f2tf(__uint_as_float(v0));
                af[mi][1] = f2tf(__uint_as_float(v1));
                af[mi][2] = f2tf(__uint_as_float(v2));
                af[mi][3] = f2tf(__uint_as_float(v3));
            }
            unsigned bf[4][2];
#pragma unroll
            for (int ni = 0; ni < 4; ni++) {
                int cb = wn * 32 + ni * 8 + gr;
                bf[ni][0] = Bs[(k0 + tig) * 68 + cb];
                bf[ni][1] = Bs[(k0 + tig + 4) * 68 + cb];
            }
#pragma unroll
            for (int mi = 0; mi < 2; mi++)
#pragma unroll
                for (int ni = 0; ni < 4; ni++)
                    mma_tf32(acc[mi][ni], af[mi], bf[ni]);
        }
    }

    __syncthreads();
    float* Asf = (float*)dsm;
    qs[t >> 5][t & 31] = g_q[b * 256 + t];

#pragma unroll
    for (int mi = 0; mi < 2; mi++) {
#pragma unroll
        for (int ni = 0; ni < 4; ni++) {
            int col = wn * 32 + ni * 8 + tig * 2;
#pragma unroll
            for (int half = 0; half < 2; half++) {
                int row = wm * 32 + mi * 16 + gr + half * 8;
                float x0 = acc[mi][ni][half * 2 + 0];
                float x1 = acc[mi][ni][half * 2 + 1];
                if (col < 32) {
                    Asf[row * 33 + col] = x0;
                    Asf[row * 33 + col + 1] = x1;
                } else {
                    g_v[((size_t)b * NQ + n0 + row) * VDQ + (col - 32)] = x0;
                    g_v[((size_t)b * NQ + n0 + row) * VDQ + (col - 31)] = x1;
                }
            }
        }
    }
    __syncthreads();

#pragma unroll
    for (int ii = 0; ii < 4; ii++) {
        int idx = ii * 256 + t;
        int h = idx & 7, n = idx >> 3;
        float s = 0.f;
#pragma unroll
        for (int kd = 0; kd < 32; kd++) s += qs[h][kd] * Asf[n * 33 + kd];
        float maskv = qm[b * NQ + n0 + n];
        g_logits[((size_t)b * HQ + h) * NQ + n0 + n] = s + 1e9f * (maskv - 1.0f);
    }
}

// ---------------- K3a/K3b/K3c ---------------------------------------------------
__global__ void k3a() {
    int b = blockIdx.x, h = blockIdx.y, t = threadIdx.x;
    const float* lrow = g_logits + ((size_t)b * HQ + h) * NQ;
    __shared__ float red[256];

    float m = -1e30f;
#pragma unroll
    for (int i = 0; i < 8; i++) m = fmaxf(m, lrow[t + i * 256]);
    red[t] = m;
    __syncthreads();
    for (int s = 128; s > 0; s >>= 1) {
        if (t < s) red[t] = fmaxf(red[t], red[t + s]);
        __syncthreads();
    }
    float mx = red[0];
    __syncthreads();

    float s = 0.f;
#pragma unroll
    for (int i = 0; i < 8; i++) s += __expf(lrow[t + i * 256] - mx);
    red[t] = s;
    __syncthreads();
    for (int st = 128; st > 0; st >>= 1) {
        if (t < st) red[t] += red[t + st];
        __syncthreads();
    }
    if (t == 0) {
        g_mx[b * 8 + h] = mx;
        g_is[b * 8 + h] = 1.0f / red[0];
    }
}

__global__ void k3b() {
    int b = blockIdx.x, ch = blockIdx.y, t = threadIdx.x;
    int lane = t & 31, wid = t >> 5;
    __shared__ float vsm[128][33];
    __shared__ float lgs[8][128];
    __shared__ float mxs[8];
    int n0 = ch * 128;

    if (t < 8) mxs[t] = g_mx[b * 8 + t];
#pragma unroll
    for (int i = 0; i < 16; i++) {
        int s = t + i * 256;
        int row = s >> 5, col = s & 31;
        vsm[row][col] = g_v[((size_t)b * NQ + n0 + row) * VDQ + col];
    }
#pragma unroll
    for (int i = 0; i < 4; i++) {
        int s = t + i * 256;
        int hh = s >> 7, n = s & 127;
        lgs[hh][n] = g_logits[((size_t)b * HQ + hh) * NQ + n0 + n];
    }
    __syncthreads();
#pragma unroll
    for (int i = 0; i < 4; i++) {
        int s = t + i * 256;
        int hh = s >> 7, n = s & 127;
        lgs[hh][n] = __expf(lgs[hh][n] - mxs[hh]);
    }
    __syncthreads();

    float acc = 0.f;
#pragma unroll 8
    for (int n = 0; n < 128; n++) acc += lgs[wid][n] * vsm[n][lane];
    g_part3[((b * 16 + ch) * 8 + wid) * 32 + lane] = acc;
}

__global__ void k3c() {
    int b = blockIdx.x, t = threadIdx.x;
    int h = t >> 5, vd = t & 31;
    float s = 0.f;
#pragma unroll
    for (int c = 0; c < 16; c++) s += g_part3[((b * 16 + c) * 8 + h) * 32 + vd];
    g_wavg[b * HV + t] = s * g_is[b * 8 + h];
}

// ---------------- K4: fp16 m16n8k16 MMA, 3-stage cp.async -----------------------
// stage: A 128 rows x 80 B = 10240; B 128 blocks x 80 B = 10240 -> 20480/stage
#define F_ST     20480
#define F_BOFF   10240
#define K4_SMEM  (3 * F_ST)

// EPI = 0: A raw fp32 (qd) via LDG+cvt+STS (reg prefetch); epilogue -> g_gated16
// EPI = 1: A fp16 image via cp.async; epilogue -> out
template <int EPI>
__global__ __launch_bounds__(256, 2) void k4_mma(const float* __restrict__ Ag,
                                                 const unsigned* __restrict__ Bp,
                                                 const float* __restrict__ bias,
                                                 float* __restrict__ Cg) {
    extern __shared__ unsigned sm[];
    unsigned char* smb = (unsigned char*)sm;
    const uint32_t sb = smem_u32(sm);

    const int tile = blockIdx.x;
    const int r0 = tile * 128;
    const int chalf = blockIdx.y;
    const int c0 = chalf * 128;
    const int t = threadIdx.x;
    const int lane = t & 31, wid = t >> 5;
    const int wm = wid >> 1, wn = wid & 1;   // 4x2 warp grid, 32x64 tiles
    const int gr = lane >> 2, tig = lane & 3;
    const int b = r0 >> 11;

    float acc[2][8][4];
#pragma unroll
    for (int mi = 0; mi < 2; mi++)
#pragma unroll
        for (int ni = 0; ni < 8; ni++)
#pragma unroll
            for (int j = 0; j < 4; j++) acc[mi][ni][j] = 0.f;

    // ---- stage issue: B always cp.async; A cp.async only for EPI=1 ----
    auto issue_stage = [&](int kc) {
        uint32_t base = sb + (kc % 3) * F_ST;
        const uint4* bsrc = (const uint4*)(Bp + (size_t)(chalf * 8 + kc) * 2048);
#pragma unroll
        for (int i = 0; i < 2; i++) {
            int q = t + i * 256;                      // 512 x 16B
            cp16(base + F_BOFF + (uint32_t)(q >> 2) * 80 + (q & 3) * 16, bsrc + q);
        }
        if (EPI == 1) {
            const uint4* asrc = (const uint4*)(g_gated16 + (size_t)(tile * 8 + kc) * 2048);
#pragma unroll
            for (int i = 0; i < 2; i++) {
                int q = t + i * 256;                  // 512 x 16B
                cp16(base + (uint32_t)(q >> 2) * 80 + (q & 3) * 16, asrc + q);
            }
        }
        cp_commit();
    };

    float4 a4[4];
    if (EPI == 0) {
#pragma unroll
        for (int i = 0; i < 4; i++) {
            int s = t + i * 256;
            int row = s >> 3, c4 = s & 7;
            a4[i] = *(const float4*)(Ag + (size_t)(r0 + row) * 256 + c4 * 4);
        }
    }
    issue_stage(0);
    issue_stage(1);

#pragma unroll 1
    for (int kc = 0; kc < 8; kc++) {
        if (kc < 7) cp_wait<1>(); else cp_wait<0>();
        __syncthreads();                 // stage kc B (and A for EPI1) visible; prior compute done
        if (kc + 2 < 8) issue_stage(kc + 2);

        unsigned char* As = smb + (kc % 3) * F_ST;
        const unsigned char* Bb = As + F_BOFF;

        if (EPI == 0) {
            // STS A chunk kc (cvt fp32 -> half2), then prefetch kc+1
#pragma unroll
            for (int i = 0; i < 4; i++) {
                int s = t + i * 256;
                int row = s >> 3, c4 = s & 7;
                uint2 w;
                w.x = pack_h2(a4[i].x, a4[i].y);
                w.y = pack_h2(a4[i].z, a4[i].w);
                *(uint2*)(As + (uint32_t)row * 80 + (c4 >> 1) * 16 + (c4 & 1) * 8) = w;
            }
            if (kc < 7) {
#pragma unroll
                for (int i = 0; i < 4; i++) {
                    int s = t + i * 256;
                    int row = s >> 3, c4 = s & 7;
                    a4[i] = *(const float4*)(Ag + (size_t)(r0 + row) * 256 + (kc + 1) * 32 + c4 * 4);
                }
            }
            __syncthreads();             // A chunk visible to all warps
        }

#pragma unroll
        for (int ks = 0; ks < 2; ks++) {   // two k16 steps per 32-chunk
            unsigned af[2][4];
#pragma unroll
            for (int mi = 0; mi < 2; mi++) {
                int rb = wm * 32 + mi * 16;
                int r1 = rb + gr, r2 = r1 + 8;
                af[mi][0] = *(const unsigned*)(As + (uint32_t)r1 * 80 + ks * 32 + 4 * tig);
                af[mi][1] = *(const unsigned*)(As + (uint32_t)r2 * 80 + ks * 32 + 4 * tig);
                af[mi][2] = *(const unsigned*)(As + (uint32_t)r1 * 80 + ks * 32 + 16 + 4 * tig);
                af[mi][3] = *(const unsigned*)(As + (uint32_t)r2 * 80 + ks * 32 + 16 + 4 * tig);
            }
            const uint4* bp = (const uint4*)(Bb + (uint32_t)((ks * 2 + wn) * 32 + lane) * 80);
            uint4 q0 = bp[0], q1 = bp[1], q2 = bp[2], q3 = bp[3];
            unsigned bf[8][2];
            bf[0][0] = q0.x; bf[0][1] = q0.y; bf[1][0] = q0.z; bf[1][1] = q0.w;
            bf[2][0] = q1.x; bf[2][1] = q1.y; bf[3][0] = q1.z; bf[3][1] = q1.w;
            bf[4][0] = q2.x; bf[4][1] = q2.y; bf[5][0] = q2.z; bf[5][1] = q2.w;
            bf[6][0] = q3.x; bf[6][1] = q3.y; bf[7][0] = q3.z; bf[7][1] = q3.w;
#pragma unroll
            for (int mi = 0; mi < 2; mi++)
#pragma unroll
                for (int ni = 0; ni < 8; ni++)
                    mma_f16(acc[mi][ni], af[mi], bf[ni]);
        }
    }

    // ---- epilogue ----
#pragma unroll
    for (int mi = 0; mi < 2; mi++) {
#pragma unroll
        for (int ni = 0; ni < 8; ni++) {
            int rowl = wm * 32 + mi * 16 + gr;
            int col = c0 + wn * 64 + ni * 8 + tig * 2;
#pragma unroll
            for (int half = 0; half < 2; half++) {
                int rl = rowl + half * 8;
                float x0 = acc[mi][ni][half * 2 + 0];
                float x1 = acc[mi][ni][half * 2 + 1];
                if (EPI == 0) {
                    float b0 = bias[col], b1 = bias[col + 1];
                    float g0 = 1.0f / (1.0f + __expf(-(x0 + b0)));
                    float g1 = 1.0f / (1.0f + __expf(-(x1 + b1)));
                    float2 w = *(const float2*)&g_wavg[b * HV + col];
                    int kcc = col >> 5, cc = col & 31;
                    g_gated16[((size_t)(tile * 8 + kcc) * 128 + rl) * 16 + (cc >> 1)] =
                        pack_h2(g0 * w.x, g1 * w.y);
                } else {
                    float2 o;
                    o.x = x0 + bias[col];
                    o.y = x1 + bias[col + 1];
                    *(float2*)&Cg[(size_t)(r0 + rl) * 256 + col] = o;
                }
            }
        }
    }
}

// ---------------- launcher ------------------------------------------------------
extern "C" void kernel_launch(void* const* d_in, const int* in_sizes, int n_in,
                              void* d_out, int out_size) {
    const float* qd = (const float*)d_in[0];
    const float* md = (const float*)d_in[1];
    const float* qm = (const float*)d_in[2];
    const float* qw = (const float*)d_in[3];
    const float* kw = (const float*)d_in[4];
    const float* vw = (const float*)d_in[5];
    const float* gw = (const float*)d_in[6];
    const float* gb = (const float*)d_in[7];
    const float* ow = (const float*)d_in[8];
    const float* ob = (const float*)d_in[9];
    float* out = (float*)d_out;

    unsigned *gwp = nullptr, *owp = nullptr;
    cudaGetSymbolAddress((void**)&gwp, g_gwp16);
    cudaGetSymbolAddress((void**)&owp, g_owp16);

    cudaFuncSetAttribute(k2_kv_logits, cudaFuncAttributeMaxDynamicSharedMemorySize, K2_SMEM);
    cudaFuncSetAttribute(k4_mma<0>, cudaFuncAttributeMaxDynamicSharedMemorySize, K4_SMEM);
    cudaFuncSetAttribute(k4_mma<1>, cudaFuncAttributeMaxDynamicSharedMemorySize, K4_SMEM);

    k0_pack16<<<256, 256>>>(gw, ow);
    k1a<<<dim3(BQ, 16), 256>>>(qd, qm);
    k1b<<<BQ, 256>>>(qw);
    k2_kv_logits<<<dim3(NQ / 128, BQ), 256, K2_SMEM>>>(md, qm, kw, vw);
    k3a<<<dim3(BQ, HQ), 256>>>();
    k3b<<<dim3(BQ, 16), 256>>>();
    k3c<<<BQ, 256>>>();
    k4_mma<0><<<dim3((BQ * NQ) / 128, HV / 128), 256, K4_SMEM>>>(qd, gwp, gb, nullptr);
    k4_mma<1><<<dim3((BQ * NQ) / 128, OQ / 128), 256, K4_SMEM>>>(nullptr, owp, ob, out);
}